// round 8
// baseline (speedup 1.0000x reference)
#include <cuda_runtime.h>
#include <cuda_bf16.h>
#include <cstddef>

// Problem constants (fixed for this problem instance)
#define NN 50000        // nodes
#define LL 4            // scales
#define EE 1600000      // nnz per sparse matrix
#define CC 128          // channels (in == out)
#define NMAT 8          // 4 phi_inverse (0..3) + 4 phi (4..7)

struct __align__(8) Edge { int col; float val; };

// -------- device scratch (no allocations allowed) --------
__device__ float g_tmp1[(size_t)LL * NN * CC];   // y  = F_l @ W          [L,N,C]
__device__ float g_tmp2[(size_t)LL * NN * CC];   // z  = phi_inv_l @ y    [L,N,C]
__device__ Edge  g_pairs[(size_t)NMAT * EE];     // CSR (col,val) pairs
__device__ int   g_hist[NMAT * NN];              // histogram / cursor
__device__ int   g_rowptr[NMAT * (NN + 1)];      // CSR row pointers

// ---------------- zero histogram ----------------
__global__ void zero_hist_kernel() {
    int i = blockIdx.x * blockDim.x + threadIdx.x;
    int stride = gridDim.x * blockDim.x;
    for (; i < NMAT * NN; i += stride) g_hist[i] = 0;
}

// ---------------- histogram of row indices ----------------
__global__ void hist_kernel(const int* __restrict__ phi_idx,
                            const int* __restrict__ pinv_idx) {
    int m = blockIdx.y;
    const int* rows = (m < 4) ? (pinv_idx + (size_t)m * 2 * EE)
                              : (phi_idx + (size_t)(m - 4) * 2 * EE);
    int* hist = g_hist + m * NN;
    int i = blockIdx.x * blockDim.x + threadIdx.x;
    int stride = gridDim.x * blockDim.x;
    for (; i < EE; i += stride) atomicAdd(&hist[rows[i]], 1);
}

// ---------------- exclusive scan (one block per matrix) ----------------
__global__ void scan_kernel() {
    const int m = blockIdx.x;
    const int tid = threadIdx.x;          // 1024 threads
    __shared__ int warp_tot[32];
    __shared__ int s_carry;
    if (tid == 0) s_carry = 0;

    int* hist = g_hist + m * NN;
    int* rp = g_rowptr + m * (NN + 1);

    for (int base = 0; base < NN; base += 1024) {
        __syncthreads();                  // protect warp_tot / s_carry reuse
        int i = base + tid;
        int x = (i < NN) ? hist[i] : 0;
        // inclusive warp scan
        int v = x;
        #pragma unroll
        for (int d = 1; d < 32; d <<= 1) {
            int t = __shfl_up_sync(0xFFFFFFFFu, v, d);
            if ((tid & 31) >= d) v += t;
        }
        if ((tid & 31) == 31) warp_tot[tid >> 5] = v;
        __syncthreads();
        if (tid < 32) {
            int wv = warp_tot[tid];
            #pragma unroll
            for (int d = 1; d < 32; d <<= 1) {
                int t = __shfl_up_sync(0xFFFFFFFFu, wv, d);
                if (tid >= d) wv += t;
            }
            warp_tot[tid] = wv;           // inclusive over warp totals
        }
        __syncthreads();
        int warp_excl = (tid >= 32) ? warp_tot[(tid >> 5) - 1] : 0;
        int excl = v + warp_excl - x;
        int carry = s_carry;
        if (i < NN) {
            rp[i] = carry + excl;
            hist[i] = 0;                  // reset for use as scatter cursor
        }
        __syncthreads();                  // all reads of s_carry done
        if (tid == 0) s_carry = carry + warp_tot[31];
    }
    __syncthreads();
    if (tid == 0) rp[NN] = s_carry;       // == EE
}

// ---------------- scatter COO -> CSR (theta folded into phi values) ----------------
__global__ void scatter_kernel(const int* __restrict__ phi_idx,
                               const float* __restrict__ phi_val,
                               const int* __restrict__ pinv_idx,
                               const float* __restrict__ pinv_val,
                               const float* __restrict__ theta) {
    int m = blockIdx.y;
    const int* rows;
    const int* cols;
    const float* vals;
    bool fold;
    if (m < 4) {
        rows = pinv_idx + (size_t)m * 2 * EE;
        cols = rows + EE;
        vals = pinv_val + (size_t)m * EE;
        fold = false;
    } else {
        int s = m - 4;
        rows = phi_idx + (size_t)s * 2 * EE;
        cols = rows + EE;
        vals = phi_val + (size_t)s * EE;
        fold = true;
    }
    const int* rp = g_rowptr + m * (NN + 1);
    int* cur = g_hist + m * NN;
    Edge* pairs = g_pairs + (size_t)m * EE;

    int i = blockIdx.x * blockDim.x + threadIdx.x;
    int stride = gridDim.x * blockDim.x;
    for (; i < EE; i += stride) {
        int r = rows[i];
        int c = cols[i];
        float v = vals[i];
        if (fold) v *= __ldg(&theta[c]);   // phi @ diag(theta)
        int pos = rp[r] + atomicAdd(&cur[r], 1);
        Edge e; e.col = c; e.val = v;
        pairs[pos] = e;
    }
}

// ---------------- dense GEMM: g_tmp1[l,n,:] = features[n,l,:] @ W ----------------
// M = N*L rows of features flattened; row m -> (n = m/L, l = m%L)
__global__ void gemm_kernel(const float* __restrict__ F,
                            const float* __restrict__ W) {
    const int BM = 64, BK = 32;
    __shared__ float As[BM][BK];
    __shared__ float Ws[BK][CC];
    int tid = threadIdx.x;          // 256
    int tx = tid & 31;              // column quad: cols [4*tx, 4*tx+4)
    int ty = tid >> 5;              // 0..7
    int m0 = blockIdx.x * BM;

    float4 acc[8];
    #pragma unroll
    for (int r = 0; r < 8; r++) acc[r] = make_float4(0.f, 0.f, 0.f, 0.f);

    for (int kt = 0; kt < CC; kt += BK) {
        // load A tile: 64x32 = 512 float4, 2 per thread
        #pragma unroll
        for (int it = 0; it < 2; it++) {
            int lin = tid + it * 256;     // float4 index
            int row = lin >> 3;           // 8 float4 per row
            int kq = lin & 7;
            *(float4*)&As[row][kq * 4] =
                *(const float4*)&F[(size_t)(m0 + row) * CC + kt + kq * 4];
        }
        // load W tile: 32x128 = 1024 float4, 4 per thread
        #pragma unroll
        for (int it = 0; it < 4; it++) {
            int lin = tid + it * 256;
            int k = lin >> 5;             // 32 float4 per row
            int cq = lin & 31;
            *(float4*)&Ws[k][cq * 4] =
                *(const float4*)&W[(size_t)(kt + k) * CC + cq * 4];
        }
        __syncthreads();
        #pragma unroll
        for (int k = 0; k < BK; k++) {
            float4 w = *(float4*)&Ws[k][tx * 4];
            #pragma unroll
            for (int rr = 0; rr < 8; rr++) {
                float a = As[ty * 8 + rr][k];
                acc[rr].x = fmaf(a, w.x, acc[rr].x);
                acc[rr].y = fmaf(a, w.y, acc[rr].y);
                acc[rr].z = fmaf(a, w.z, acc[rr].z);
                acc[rr].w = fmaf(a, w.w, acc[rr].w);
            }
        }
        __syncthreads();
    }
    #pragma unroll
    for (int rr = 0; rr < 8; rr++) {
        int m = m0 + ty * 8 + rr;
        int n = m >> 2;                   // m / L
        int l = m & 3;                    // m % L
        *(float4*)&g_tmp1[((size_t)l * NN + n) * CC + tx * 4] = acc[rr];
    }
}

// ---------------- CSR gather spmm: out_row = sum_e val * y[col] ----------------
// stage 0: y = g_tmp1, out = g_tmp2 (layout [L,N,C]), mats 0..3 (phi_inv)
// stage 1: y = g_tmp2, out = d_out (layout [N,L,C]), mats 4..7 (phi, theta folded)
__global__ void gather_kernel(float* __restrict__ ext_out, int stage) {
    int scale = blockIdx.y;
    int m = (stage == 0) ? scale : (4 + scale);
    int warp = threadIdx.x >> 5;
    int lane = threadIdx.x & 31;
    int row = blockIdx.x * (blockDim.x >> 5) + warp;
    if (row >= NN) return;

    const float* y = (stage == 0) ? g_tmp1 : g_tmp2;
    const int* rp = g_rowptr + m * (NN + 1);
    int start = rp[row];
    int end = rp[row + 1];
    const float* ysl = y + (size_t)scale * NN * CC;
    const Edge* ep = g_pairs + (size_t)m * EE;
    const int c4 = lane * 4;

    float4 acc = make_float4(0.f, 0.f, 0.f, 0.f);
    int j = start;
    for (; j + 4 <= end; j += 4) {
        Edge e0 = ep[j], e1 = ep[j + 1], e2 = ep[j + 2], e3 = ep[j + 3];
        float4 v0 = *(const float4*)(ysl + (size_t)e0.col * CC + c4);
        float4 v1 = *(const float4*)(ysl + (size_t)e1.col * CC + c4);
        float4 v2 = *(const float4*)(ysl + (size_t)e2.col * CC + c4);
        float4 v3 = *(const float4*)(ysl + (size_t)e3.col * CC + c4);
        acc.x = fmaf(e0.val, v0.x, acc.x); acc.y = fmaf(e0.val, v0.y, acc.y);
        acc.z = fmaf(e0.val, v0.z, acc.z); acc.w = fmaf(e0.val, v0.w, acc.w);
        acc.x = fmaf(e1.val, v1.x, acc.x); acc.y = fmaf(e1.val, v1.y, acc.y);
        acc.z = fmaf(e1.val, v1.z, acc.z); acc.w = fmaf(e1.val, v1.w, acc.w);
        acc.x = fmaf(e2.val, v2.x, acc.x); acc.y = fmaf(e2.val, v2.y, acc.y);
        acc.z = fmaf(e2.val, v2.z, acc.z); acc.w = fmaf(e2.val, v2.w, acc.w);
        acc.x = fmaf(e3.val, v3.x, acc.x); acc.y = fmaf(e3.val, v3.y, acc.y);
        acc.z = fmaf(e3.val, v3.z, acc.z); acc.w = fmaf(e3.val, v3.w, acc.w);
    }
    for (; j < end; j++) {
        Edge e = ep[j];
        float4 v = *(const float4*)(ysl + (size_t)e.col * CC + c4);
        acc.x = fmaf(e.val, v.x, acc.x); acc.y = fmaf(e.val, v.y, acc.y);
        acc.z = fmaf(e.val, v.z, acc.z); acc.w = fmaf(e.val, v.w, acc.w);
    }

    float* dst = (stage == 0)
        ? (g_tmp2 + ((size_t)scale * NN + row) * CC + c4)
        : (ext_out + ((size_t)row * LL + scale) * CC + c4);
    *(float4*)dst = acc;
}

extern "C" void kernel_launch(void* const* d_in, const int* in_sizes, int n_in,
                              void* d_out, int out_size) {
    const int*   phi_idx  = (const int*)d_in[0];     // [L,2,E]
    const float* phi_val  = (const float*)d_in[1];   // [L,E]
    const int*   pinv_idx = (const int*)d_in[2];     // [L,2,E]
    const float* pinv_val = (const float*)d_in[3];   // [L,E]
    const float* feats    = (const float*)d_in[4];   // [N,L,C]
    const float* Wm       = (const float*)d_in[5];   // [C,C]
    const float* theta    = (const float*)d_in[6];   // [N]
    float* out = (float*)d_out;                      // [N,L,C]

    // 1) reset cursors/histogram
    zero_hist_kernel<<<256, 1024>>>();
    // 2) per-matrix row histogram
    hist_kernel<<<dim3(512, NMAT), 256>>>(phi_idx, pinv_idx);
    // 3) exclusive scan -> row_ptr (also zeroes hist for cursor use)
    scan_kernel<<<NMAT, 1024>>>();
    // 4) scatter COO -> CSR pairs (theta folded into phi values)
    scatter_kernel<<<dim3(512, NMAT), 256>>>(phi_idx, phi_val, pinv_idx, pinv_val, theta);
    // 5) dense GEMM: g_tmp1 = F @ W  (per scale)
    gemm_kernel<<<(NN * LL) / 64, 256>>>(feats, Wm);
    // 6) spmm gather: g_tmp2 = phi_inv @ g_tmp1  (16 warps/CTA)
    gather_kernel<<<dim3((NN + 15) / 16, LL), 512>>>(out, 0);
    // 7) spmm gather: out = phi @ diag(theta) @ g_tmp2  (theta already folded)
    gather_kernel<<<dim3((NN + 15) / 16, LL), 512>>>(out, 1);
}